// round 13
// baseline (speedup 1.0000x reference)
#include <cuda_runtime.h>
#include <cuda_fp16.h>
#include <math.h>
#include <stdint.h>

#define BSZ_ 8
#define LEN_ 8192
#define PDIM 128
#define HDIM 128
#define CH 64
#define NC (LEN_/CH)          // 128
#define MROWS (BSZ_*LEN_)     // 65536
#define PA 136                // smem pitch (halfs) for K=128 tiles
#define PY 264                // smem pitch (halfs) for K=256 ys tile
#define PB 136                // smem pitch (halfs) for W half-tiles

// ---------------- scratch ----------------------------------------------------
__device__ float4 g_csum[BSZ_*NC*PDIM];            // 2 MB
__device__ float4 g_cin [BSZ_*NC*PDIM];            // 2 MB
__device__ float4 g_M  [PDIM];
__device__ float2 g_c  [PDIM];
__device__ float4 g_Mp [PDIM];                     // M^CH
__device__ __half g_W1t[HDIM*2*PDIM];              // [k=h][n=2p+ri]
__device__ __half g_W2t[2*PDIM*HDIM];              // [k=2p+ri][n=h] (sign folded)

// ---------------- helpers ----------------------------------------------------
__device__ __forceinline__ uint32_t smem_u32(const void* p) {
    uint32_t a;
    asm("{ .reg .u64 t; cvta.to.shared.u64 t, %1; cvt.u32.u64 %0, t; }" : "=r"(a) : "l"(p));
    return a;
}
__device__ __forceinline__ void ldsm4(uint32_t addr, uint32_t* r) {
    asm volatile("ldmatrix.sync.aligned.m8n8.x4.shared.b16 {%0,%1,%2,%3}, [%4];"
                 : "=r"(r[0]), "=r"(r[1]), "=r"(r[2]), "=r"(r[3]) : "r"(addr));
}
__device__ __forceinline__ void ldsm4t(uint32_t addr, uint32_t* r) {
    asm volatile("ldmatrix.sync.aligned.m8n8.x4.trans.shared.b16 {%0,%1,%2,%3}, [%4];"
                 : "=r"(r[0]), "=r"(r[1]), "=r"(r[2]), "=r"(r[3]) : "r"(addr));
}
__device__ __forceinline__ void mma_f16(float* d, const uint32_t* a, const uint32_t* b) {
    asm volatile(
        "mma.sync.aligned.m16n8k16.row.col.f32.f16.f16.f32 "
        "{%0,%1,%2,%3}, {%4,%5,%6,%7}, {%8,%9}, {%0,%1,%2,%3};"
        : "+f"(d[0]), "+f"(d[1]), "+f"(d[2]), "+f"(d[3])
        : "r"(a[0]), "r"(a[1]), "r"(a[2]), "r"(a[3]), "r"(b[0]), "r"(b[1]));
}

// ---------------- prep (parallel: 32 blocks) ----------------------------------
__global__ void prep_kernel(const float* __restrict__ Ad, const float* __restrict__ Gd,
                            const float* __restrict__ dtv,
                            const float* __restrict__ Bin, const float* __restrict__ Cin) {
    int tid = threadIdx.x;
    int gtid = blockIdx.x * blockDim.x + tid;
    int gstride = gridDim.x * blockDim.x;
    if (blockIdx.x == 0 && tid < PDIM) {
        int p = tid;
        float dts = 1.0f / (1.0f + expf(-dtv[p]));
        float A   = fmaxf(Ad[p], 0.0f);
        float G   = fmaxf(Gd[p], 0.0f);
        float dt2 = fmaxf(dts*dts, 1e-6f);
        float s   = sqrtf(1.0f + dts*G);
        float alo = (2.0f + dts*G - 2.0f*s) / dt2;
        float ahi = (2.0f + dts*G + 2.0f*s) / dt2;
        float Af  = fminf(fmaxf(A, alo), ahi);
        float S    = 1.0f + dts*G;
        float invS = 1.0f / S;
        float m11 = invS;
        float m12 = -dts*invS*Af;
        float m21 = dts*invS;
        float m22 = 1.0f - dts*dts*invS*Af;
        g_M[p] = make_float4(m11, m12, m21, m22);
        g_c[p] = make_float2(dts*invS, dts*dts*invS);
        float a = m11, b = m12, c = m21, d = m22;
        #pragma unroll
        for (int i = 0; i < 6; i++) {   // M^64
            float na = a*a + b*c;
            float nb = a*b + b*d;
            float nc = c*a + d*c;
            float nd = c*b + d*d;
            a = na; b = nb; c = nc; d = nd;
        }
        g_Mp[p] = make_float4(a, b, c, d);
    }
    for (int idx = gtid; idx < HDIM*2*PDIM; idx += gstride) {
        int h = idx / (2*PDIM), n = idx % (2*PDIM);
        int p = n >> 1, ri = n & 1;
        g_W1t[idx] = __float2half(Bin[((size_t)p*HDIM + h)*2 + ri]);
    }
    for (int idx = gtid; idx < 2*PDIM*HDIM; idx += gstride) {
        int k = idx / HDIM, h = idx % HDIM;
        float v = Cin[(size_t)h*2*PDIM + k];
        g_W2t[idx] = __float2half((k & 1) ? -v : v);
    }
}

// ---------------- GEMM1 partials: x @ W1 -> chunk partial sums only -----------
// CTA tile 128 rows = 2 chunks of CH=64; writes csum (no Bu store)
__global__ void __launch_bounds__(256, 2)
gemm1_kernel(const float* __restrict__ x) {
    extern __shared__ __align__(16) char smem[];
    __half* Ah = (__half*)smem;                    // [128][PA]
    __half* Bh = (__half*)(smem + 128*PA*2);       // [128][PA]
    float*  stage = (float*)smem;                  // alias, [128][130]
    uint32_t sA = smem_u32(Ah), sB = smem_u32(Bh);
    int tid = threadIdx.x, lane = tid & 31, wid = tid >> 5;
    int wm = wid >> 1, wn = wid & 1;
    int g = lane >> 2, t = lane & 3;
    int bm = blockIdx.y * 128, bn = blockIdx.x * 128;
    uint32_t arow = (uint32_t)(lane & 15);
    uint32_t asel = (uint32_t)((lane >> 4) * 8);

    #pragma unroll
    for (int i = 0; i < 16; i++) {
        int flat = i*256 + tid;
        int row = flat >> 5, c4 = flat & 31;
        float4 v = *(const float4*)&x[(size_t)(bm + row)*128 + c4*4];
        *(__half2*)&Ah[row*PA + c4*4]     = __floats2half2_rn(v.x, v.y);
        *(__half2*)&Ah[row*PA + c4*4 + 2] = __floats2half2_rn(v.z, v.w);
    }
    #pragma unroll
    for (int i = 0; i < 8; i++) {
        int flat = i*256 + tid;
        int k = flat >> 4, ch = flat & 15;
        *(uint4*)&Bh[k*PA + ch*8] = *(const uint4*)&g_W1t[(size_t)k*2*PDIM + bn + ch*8];
    }
    __syncthreads();

    float acc[2][8][4] = {};
    #pragma unroll
    for (int ks = 0; ks < 8; ks++) {
        int k0 = ks*16;
        uint32_t a[2][4], b[8][2];
        #pragma unroll
        for (int mf = 0; mf < 2; mf++)
            ldsm4(sA + ((wm*32 + mf*16 + arow)*PA + k0 + asel)*2, a[mf]);
        #pragma unroll
        for (int np = 0; np < 4; np++) {
            uint32_t r[4];
            ldsm4t(sB + ((k0 + arow)*PA + wn*64 + np*16 + asel)*2, r);
            b[np*2][0] = r[0]; b[np*2][1] = r[1];
            b[np*2+1][0] = r[2]; b[np*2+1][1] = r[3];
        }
        #pragma unroll
        for (int mf = 0; mf < 2; mf++)
            #pragma unroll
            for (int nf = 0; nf < 8; nf++)
                mma_f16(acc[mf][nf], a[mf], b[nf]);
    }

    // stage acc to smem (A/B tiles dead)
    __syncthreads();
    #pragma unroll
    for (int mf = 0; mf < 2; mf++) {
        int rl = wm*32 + mf*16 + g;
        #pragma unroll
        for (int nf = 0; nf < 8; nf++) {
            int cl = wn*64 + nf*8 + 2*t;
            *(float2*)&stage[rl*130 + cl]     = make_float2(acc[mf][nf][0], acc[mf][nf][1]);
            *(float2*)&stage[(rl+8)*130 + cl] = make_float2(acc[mf][nf][2], acc[mf][nf][3]);
        }
    }
    __syncthreads();

    // chunk-partial scans: 2 chunks of 64 rows, threads 0-127
    int pbase = bn >> 1;
    if (tid < 128) {
        int pl = tid & 63;             // local p
        int sub = tid >> 6;            // which 64-row chunk
        int pg = pbase + pl;
        float4 Mv = g_M[pg];
        float2 cv = g_c[pg];
        float h1r = 0.f, h1i = 0.f, h2r = 0.f, h2i = 0.f;
        #pragma unroll 8
        for (int l = 0; l < CH; l++) {
            float2 bu = *(float2*)&stage[(sub*64 + l)*130 + 2*pl];
            float n1r = Mv.x*h1r + Mv.y*h2r + cv.x*bu.x;
            float n1i = Mv.x*h1i + Mv.y*h2i + cv.x*bu.y;
            float n2r = Mv.z*h1r + Mv.w*h2r + cv.y*bu.x;
            float n2i = Mv.z*h1i + Mv.w*h2i + cv.y*bu.y;
            h1r = n1r; h1i = n1i; h2r = n2r; h2i = n2i;
        }
        int b = blockIdx.y >> 6;
        int cc = (blockIdx.y & 63)*2 + sub;
        g_csum[(b*NC + cc)*PDIM + pg] = make_float4(h1r, h1i, h2r, h2i);
    }
}

// ---------------- carry: scan over NC=128 chunks with M^CH (batch 16) ---------
__global__ void scan_carry_kernel() {
    int p = threadIdx.x;
    int b = blockIdx.x;
    float4 Mp = g_Mp[p];
    float h1r = 0.f, h1i = 0.f, h2r = 0.f, h2i = 0.f;
    for (int c0 = 0; c0 < NC; c0 += 16) {
        float4 s[16];
        #pragma unroll
        for (int j = 0; j < 16; j++)
            s[j] = g_csum[(b*NC + c0 + j)*PDIM + p];
        #pragma unroll
        for (int j = 0; j < 16; j++) {
            g_cin[(b*NC + c0 + j)*PDIM + p] = make_float4(h1r, h1i, h2r, h2i);
            float n1r = Mp.x*h1r + Mp.y*h2r + s[j].x;
            float n1i = Mp.x*h1i + Mp.y*h2i + s[j].y;
            float n2r = Mp.z*h1r + Mp.w*h2r + s[j].z;
            float n2i = Mp.z*h1i + Mp.w*h2i + s[j].w;
            h1r = n1r; h1i = n1i; h2r = n2r; h2i = n2i;
        }
    }
}

// ---------------- fused final: recompute Bu + scan + GEMM2 + D*x --------------
// SMEM (84 KB -> 2 CTAs/SM): Ah [64][PA] half (17408B, x tile)
//                            Ys [64][PY] half (33792B, Bu then ys)
//                            Wh [128][PB] half (34816B, W1/W2 halves)
__global__ void __launch_bounds__(256, 2)
fused_final_kernel(float* __restrict__ outp, const float* __restrict__ x,
                   const float* __restrict__ Dv) {
    extern __shared__ __align__(16) char smem[];
    __half* Ah = (__half*)smem;                          // 17408 B
    __half* Ys = (__half*)(smem + 17408);                // 33792 B
    __half* Wh = (__half*)(smem + 17408 + 33792);        // 34816 B
    uint32_t sA = smem_u32(Ah), sY = smem_u32(Ys), sW = smem_u32(Wh);
    int tid = threadIdx.x, lane = tid & 31, wid = tid >> 5;
    int wm = wid >> 1, wn = wid & 1;
    int g = lane >> 2, t = lane & 3;
    int c = blockIdx.x, b = blockIdx.y;
    int bm = b*LEN_ + c*CH;                              // global row base (64 rows)
    uint32_t arow = (uint32_t)(lane & 15);
    uint32_t asel = (uint32_t)((lane >> 4) * 8);

    // incoming state for this chunk (threads 0-127, one per p)
    float4 hin;
    if (tid < 128) hin = g_cin[(b*NC + c)*PDIM + tid];

    // load x tile (64 rows x 128 fp32) -> Ah half
    #pragma unroll
    for (int i = 0; i < 8; i++) {
        int flat = i*256 + tid;
        int row = flat >> 5, c4 = flat & 31;
        float4 v = *(const float4*)&x[(size_t)(bm + row)*128 + c4*4];
        *(__half2*)&Ah[row*PA + c4*4]     = __floats2half2_rn(v.x, v.y);
        *(__half2*)&Ah[row*PA + c4*4 + 2] = __floats2half2_rn(v.z, v.w);
    }
    // load W1 N-half 0 (k=0..127, n=0..127)
    #pragma unroll
    for (int i = 0; i < 8; i++) {
        int flat = i*256 + tid;
        int k = flat >> 4, ch = flat & 15;
        *(uint4*)&Wh[k*PB + ch*8] = *(const uint4*)&g_W1t[(size_t)k*2*PDIM + ch*8];
    }
    __syncthreads();

    // MMA1: Bu(64 x 256) = x(64 x 128) @ W1^T, in two N=128 phases -> stage to Ys
    #pragma unroll
    for (int nh = 0; nh < 2; nh++) {
        float acc[8][4] = {};
        #pragma unroll
        for (int ks = 0; ks < 8; ks++) {
            int k0 = ks*16;
            uint32_t a[4], bfr[8][2];
            ldsm4(sA + ((wm*16 + arow)*PA + k0 + asel)*2, a);
            #pragma unroll
            for (int np = 0; np < 4; np++) {
                uint32_t rr[4];
                ldsm4t(sW + ((k0 + arow)*PB + wn*64 + np*16 + asel)*2, rr);
                bfr[np*2][0] = rr[0]; bfr[np*2][1] = rr[1];
                bfr[np*2+1][0] = rr[2]; bfr[np*2+1][1] = rr[3];
            }
            #pragma unroll
            for (int nf = 0; nf < 8; nf++)
                mma_f16(acc[nf], a, bfr[nf]);
        }
        // stage Bu to Ys (half), cols nh*128 + ...
        int rl = wm*16 + g;
        #pragma unroll
        for (int nf = 0; nf < 8; nf++) {
            int col = nh*128 + wn*64 + nf*8 + 2*t;
            *(__half2*)&Ys[rl*PY + col]     = __floats2half2_rn(acc[nf][0], acc[nf][1]);
            *(__half2*)&Ys[(rl+8)*PY + col] = __floats2half2_rn(acc[nf][2], acc[nf][3]);
        }
        __syncthreads();
        if (nh == 0) {
            // load W1 N-half 1
            #pragma unroll
            for (int i = 0; i < 8; i++) {
                int flat = i*256 + tid;
                int k = flat >> 4, ch = flat & 15;
                *(uint4*)&Wh[k*PB + ch*8] =
                    *(const uint4*)&g_W1t[(size_t)k*2*PDIM + 128 + ch*8];
            }
            __syncthreads();
        }
    }

    if (tid < 128) {
        // serial scan from SMEM (64 steps), overwrite bu with ys (half) in place
        int p = tid;
        float4 Mv = g_M[p];
        float2 cv = g_c[p];
        float h1r = hin.x, h1i = hin.y, h2r = hin.z, h2i = hin.w;
        #pragma unroll 8
        for (int l = 0; l < CH; l++) {
            __half2* slot = (__half2*)&Ys[l*PY + 2*p];
            float2 bu = __half22float2(*slot);
            float n1r = Mv.x*h1r + Mv.y*h2r + cv.x*bu.x;
            float n1i = Mv.x*h1i + Mv.y*h2i + cv.x*bu.y;
            float n2r = Mv.z*h1r + Mv.w*h2r + cv.y*bu.x;
            float n2i = Mv.z*h1i + Mv.w*h2i + cv.y*bu.y;
            h1r = n1r; h1i = n1i; h2r = n2r; h2i = n2i;
            *slot = __floats2half2_rn(h2r, h2i);
        }
    } else {
        // warps 4-7: load W2 K-half 0 (128 rows x 128 halfs = 2048 uint4)
        int t2 = tid - 128;
        #pragma unroll
        for (int i = 0; i < 16; i++) {
            int flat = i*128 + t2;
            int k = flat >> 4, ch = flat & 15;
            *(uint4*)&Wh[k*PB + ch*8] = *(const uint4*)&g_W2t[(size_t)k*HDIM + ch*8];
        }
    }
    __syncthreads();

    // GEMM2: out(64 x 128) = ys(64 x 256) @ W2^T, K=256 in two K=128 phases
    float acc[8][4] = {};
    #pragma unroll
    for (int r = 0; r < 2; r++) {
        if (r) {
            __syncthreads();   // phase-0 mma reads of Wh complete
            #pragma unroll
            for (int i = 0; i < 8; i++) {
                int flat = i*256 + tid;
                int k = flat >> 4, ch = flat & 15;
                *(uint4*)&Wh[k*PB + ch*8] =
                    *(const uint4*)&g_W2t[(size_t)(128 + k)*HDIM + ch*8];
            }
            __syncthreads();
        }
        #pragma unroll
        for (int ks = 0; ks < 8; ks++) {
            int k0 = ks*16;
            uint32_t a[4], bfr[8][2];
            ldsm4(sY + ((wm*16 + arow)*PY + r*128 + k0 + asel)*2, a);
            #pragma unroll
            for (int np = 0; np < 4; np++) {
                uint32_t rr[4];
                ldsm4t(sW + ((k0 + arow)*PB + wn*64 + np*16 + asel)*2, rr);
                bfr[np*2][0] = rr[0]; bfr[np*2][1] = rr[1];
                bfr[np*2+1][0] = rr[2]; bfr[np*2+1][1] = rr[3];
            }
            #pragma unroll
            for (int nf = 0; nf < 8; nf++)
                mma_f16(acc[nf], a, bfr[nf]);
        }
    }

    {
        int row = bm + wm*16 + g;
        #pragma unroll
        for (int nf = 0; nf < 8; nf++) {
            int col = wn*64 + nf*8 + 2*t;
            float2 d0 = *(const float2*)&Dv[col];
            float2 x0 = *(const float2*)&x[(size_t)row*128 + col];
            float2 x1 = *(const float2*)&x[(size_t)(row+8)*128 + col];
            float2 o0 = make_float2(acc[nf][0] + d0.x*x0.x, acc[nf][1] + d0.y*x0.y);
            float2 o1 = make_float2(acc[nf][2] + d0.x*x1.x, acc[nf][3] + d0.y*x1.y);
            *(float2*)&outp[(size_t)row*128 + col]     = o0;
            *(float2*)&outp[(size_t)(row+8)*128 + col] = o1;
        }
    }
}

// ---------------- launch ------------------------------------------------------
extern "C" void kernel_launch(void* const* d_in, const int* in_sizes, int n_in,
                              void* d_out, int out_size) {
    const float* x  = (const float*)d_in[0];
    const float* Ad = (const float*)d_in[1];
    const float* Gd = (const float*)d_in[2];
    const float* dt = (const float*)d_in[3];
    const float* B  = (const float*)d_in[4];
    const float* C  = (const float*)d_in[5];
    const float* D  = (const float*)d_in[6];
    float* out = (float*)d_out;

    const int SMEM1 = 2 * 128 * PA * 2;                 // 69632
    const int SMEMF = 17408 + 33792 + 34816;            // 86016
    cudaFuncSetAttribute(gemm1_kernel, cudaFuncAttributeMaxDynamicSharedMemorySize, SMEM1);
    cudaFuncSetAttribute(fused_final_kernel, cudaFuncAttributeMaxDynamicSharedMemorySize, SMEMF);

    prep_kernel<<<32, 256>>>(Ad, Gd, dt, B, C);
    gemm1_kernel<<<dim3(2, MROWS/128), 256, SMEM1>>>(x);
    scan_carry_kernel<<<BSZ_, 128>>>();
    fused_final_kernel<<<dim3(NC, BSZ_), 256, SMEMF>>>(out, x, D);
}

// round 16
// speedup vs baseline: 1.1826x; 1.1826x over previous
#include <cuda_runtime.h>
#include <cuda_fp16.h>
#include <math.h>
#include <stdint.h>

#define BSZ_ 8
#define LEN_ 8192
#define PDIM 128
#define HDIM 128
#define CH 64
#define NC (LEN_/CH)          // 128
#define MROWS (BSZ_*LEN_)     // 65536
#define PA 136                // smem pitch (halfs) for K=128 tiles
#define PY 264                // smem pitch (halfs) for K=256 ys tile
#define PB 136                // smem pitch (halfs) for W half-tiles
#define PS 136                // smem pitch (halfs) for gemm1 half-staging

// ---------------- scratch ----------------------------------------------------
__device__ __half2 g_Buh[(size_t)MROWS*PDIM];      // 32 MB Bu as half2 (row, p)
__device__ float4 g_csum[BSZ_*NC*PDIM];            // 2 MB
__device__ float4 g_cin [BSZ_*NC*PDIM];            // 2 MB
__device__ float4 g_M  [PDIM];
__device__ float2 g_c  [PDIM];
__device__ float4 g_Mp [PDIM];                     // M^CH
__device__ __half g_W1t[HDIM*2*PDIM];              // [k=h][n=2p+ri]
__device__ __half g_W2t[2*PDIM*HDIM];              // [k=2p+ri][n=h] (sign folded)

// ---------------- helpers ----------------------------------------------------
__device__ __forceinline__ uint32_t smem_u32(const void* p) {
    uint32_t a;
    asm("{ .reg .u64 t; cvta.to.shared.u64 t, %1; cvt.u32.u64 %0, t; }" : "=r"(a) : "l"(p));
    return a;
}
__device__ __forceinline__ void ldsm4(uint32_t addr, uint32_t* r) {
    asm volatile("ldmatrix.sync.aligned.m8n8.x4.shared.b16 {%0,%1,%2,%3}, [%4];"
                 : "=r"(r[0]), "=r"(r[1]), "=r"(r[2]), "=r"(r[3]) : "r"(addr));
}
__device__ __forceinline__ void ldsm4t(uint32_t addr, uint32_t* r) {
    asm volatile("ldmatrix.sync.aligned.m8n8.x4.trans.shared.b16 {%0,%1,%2,%3}, [%4];"
                 : "=r"(r[0]), "=r"(r[1]), "=r"(r[2]), "=r"(r[3]) : "r"(addr));
}
__device__ __forceinline__ void mma_f16(float* d, const uint32_t* a, const uint32_t* b) {
    asm volatile(
        "mma.sync.aligned.m16n8k16.row.col.f32.f16.f16.f32 "
        "{%0,%1,%2,%3}, {%4,%5,%6,%7}, {%8,%9}, {%0,%1,%2,%3};"
        : "+f"(d[0]), "+f"(d[1]), "+f"(d[2]), "+f"(d[3])
        : "r"(a[0]), "r"(a[1]), "r"(a[2]), "r"(a[3]), "r"(b[0]), "r"(b[1]));
}

// ---------------- prep (parallel: 32 blocks) ----------------------------------
__global__ void prep_kernel(const float* __restrict__ Ad, const float* __restrict__ Gd,
                            const float* __restrict__ dtv,
                            const float* __restrict__ Bin, const float* __restrict__ Cin) {
    int tid = threadIdx.x;
    int gtid = blockIdx.x * blockDim.x + tid;
    int gstride = gridDim.x * blockDim.x;
    if (blockIdx.x == 0 && tid < PDIM) {
        int p = tid;
        float dts = 1.0f / (1.0f + expf(-dtv[p]));
        float A   = fmaxf(Ad[p], 0.0f);
        float G   = fmaxf(Gd[p], 0.0f);
        float dt2 = fmaxf(dts*dts, 1e-6f);
        float s   = sqrtf(1.0f + dts*G);
        float alo = (2.0f + dts*G - 2.0f*s) / dt2;
        float ahi = (2.0f + dts*G + 2.0f*s) / dt2;
        float Af  = fminf(fmaxf(A, alo), ahi);
        float S    = 1.0f + dts*G;
        float invS = 1.0f / S;
        float m11 = invS;
        float m12 = -dts*invS*Af;
        float m21 = dts*invS;
        float m22 = 1.0f - dts*dts*invS*Af;
        g_M[p] = make_float4(m11, m12, m21, m22);
        g_c[p] = make_float2(dts*invS, dts*dts*invS);
        float a = m11, b = m12, c = m21, d = m22;
        #pragma unroll
        for (int i = 0; i < 6; i++) {   // M^64
            float na = a*a + b*c;
            float nb = a*b + b*d;
            float nc = c*a + d*c;
            float nd = c*b + d*d;
            a = na; b = nb; c = nc; d = nd;
        }
        g_Mp[p] = make_float4(a, b, c, d);
    }
    for (int idx = gtid; idx < HDIM*2*PDIM; idx += gstride) {
        int h = idx / (2*PDIM), n = idx % (2*PDIM);
        int p = n >> 1, ri = n & 1;
        g_W1t[idx] = __float2half(Bin[((size_t)p*HDIM + h)*2 + ri]);
    }
    for (int idx = gtid; idx < 2*PDIM*HDIM; idx += gstride) {
        int k = idx / HDIM, h = idx % HDIM;
        float v = Cin[(size_t)h*2*PDIM + k];
        g_W2t[idx] = __float2half((k & 1) ? -v : v);
    }
}

// ---------------- GEMM1: one x pass, N=256 in two phases ----------------------
// SMEM: Ah [128][PA] (34816B, persists) | Wh [128][PB] (34816B, W1 N-half)
//       Sh [128][PS] (34816B, half staging)  => 104448 B, 2 CTAs/SM
__global__ void __launch_bounds__(256, 2)
gemm1_kernel(const float* __restrict__ x) {
    extern __shared__ __align__(16) char smem[];
    __half* Ah = (__half*)smem;                          // x tile
    __half* Wh = (__half*)(smem + 34816);                // W1 N-half
    __half* Sh = (__half*)(smem + 69632);                // Bu staging (half)
    uint32_t sA = smem_u32(Ah), sB = smem_u32(Wh);
    int tid = threadIdx.x, lane = tid & 31, wid = tid >> 5;
    int wm = wid >> 1, wn = wid & 1;
    int g = lane >> 2, t = lane & 3;
    int bm = blockIdx.x * 128;
    uint32_t arow = (uint32_t)(lane & 15);
    uint32_t asel = (uint32_t)((lane >> 4) * 8);

    // load x tile (128 x 128 fp32) -> Ah half
    #pragma unroll
    for (int i = 0; i < 16; i++) {
        int flat = i*256 + tid;
        int row = flat >> 5, c4 = flat & 31;
        float4 v = *(const float4*)&x[(size_t)(bm + row)*128 + c4*4];
        *(__half2*)&Ah[row*PA + c4*4]     = __floats2half2_rn(v.x, v.y);
        *(__half2*)&Ah[row*PA + c4*4 + 2] = __floats2half2_rn(v.z, v.w);
    }
    // load W1 N-half 0
    #pragma unroll
    for (int i = 0; i < 8; i++) {
        int flat = i*256 + tid;
        int k = flat >> 4, ch = flat & 15;
        *(uint4*)&Wh[k*PB + ch*8] = *(const uint4*)&g_W1t[(size_t)k*2*PDIM + ch*8];
    }
    __syncthreads();

    #pragma unroll
    for (int nh = 0; nh < 2; nh++) {
        // MMA: (128 x 128) = x @ W1half^T
        float acc[2][8][4] = {};
        #pragma unroll
        for (int ks = 0; ks < 8; ks++) {
            int k0 = ks*16;
            uint32_t a[2][4], bfr[8][2];
            #pragma unroll
            for (int mf = 0; mf < 2; mf++)
                ldsm4(sA + ((wm*32 + mf*16 + arow)*PA + k0 + asel)*2, a[mf]);
            #pragma unroll
            for (int np = 0; np < 4; np++) {
                uint32_t rr[4];
                ldsm4t(sB + ((k0 + arow)*PB + wn*64 + np*16 + asel)*2, rr);
                bfr[np*2][0] = rr[0]; bfr[np*2][1] = rr[1];
                bfr[np*2+1][0] = rr[2]; bfr[np*2+1][1] = rr[3];
            }
            #pragma unroll
            for (int mf = 0; mf < 2; mf++)
                #pragma unroll
                for (int nf = 0; nf < 8; nf++)
                    mma_f16(acc[mf][nf], a[mf], bfr[nf]);
        }

        // stage acc -> Sh as half
        #pragma unroll
        for (int mf = 0; mf < 2; mf++) {
            int rl = wm*32 + mf*16 + g;
            #pragma unroll
            for (int nf = 0; nf < 8; nf++) {
                int cl = wn*64 + nf*8 + 2*t;
                *(__half2*)&Sh[rl*PS + cl]     = __floats2half2_rn(acc[mf][nf][0], acc[mf][nf][1]);
                *(__half2*)&Sh[(rl+8)*PS + cl] = __floats2half2_rn(acc[mf][nf][2], acc[mf][nf][3]);
            }
        }
        __syncthreads();

        if (tid < 128) {
            // chunk-partial scans for p in [nh*64, nh*64+64)
            int pl = tid & 63;
            int sub = tid >> 6;
            int pg = nh*64 + pl;
            float4 Mv = g_M[pg];
            float2 cv = g_c[pg];
            float h1r = 0.f, h1i = 0.f, h2r = 0.f, h2i = 0.f;
            #pragma unroll 8
            for (int l = 0; l < CH; l++) {
                float2 bu = __half22float2(*(__half2*)&Sh[(sub*64 + l)*PS + 2*pl]);
                float n1r = Mv.x*h1r + Mv.y*h2r + cv.x*bu.x;
                float n1i = Mv.x*h1i + Mv.y*h2i + cv.x*bu.y;
                float n2r = Mv.z*h1r + Mv.w*h2r + cv.y*bu.x;
                float n2i = Mv.z*h1i + Mv.w*h2i + cv.y*bu.y;
                h1r = n1r; h1i = n1i; h2r = n2r; h2i = n2i;
            }
            int b = blockIdx.x >> 6;
            int cc = (blockIdx.x & 63)*2 + sub;
            g_csum[(b*NC + cc)*PDIM + pg] = make_float4(h1r, h1i, h2r, h2i);
        } else {
            int t2 = tid - 128;
            // write Buh for this phase: 128 rows x 16 uint4 (p-half)
            #pragma unroll
            for (int i = 0; i < 16; i++) {
                int flat = i*128 + t2;
                int row = flat >> 4, j = flat & 15;
                uint4 v = *(uint4*)&Sh[row*PS + j*8];
                *(uint4*)&g_Buh[(size_t)(bm + row)*PDIM + nh*64 + j*4] = v;
            }
            // load W1 N-half 1 for the next phase
            if (nh == 0) {
                #pragma unroll
                for (int i = 0; i < 16; i++) {
                    int flat = i*128 + t2;
                    int k = flat >> 4, ch = flat & 15;
                    *(uint4*)&Wh[k*PB + ch*8] =
                        *(const uint4*)&g_W1t[(size_t)k*2*PDIM + 128 + ch*8];
                }
            }
        }
        __syncthreads();
    }
}

// ---------------- carry: scan over NC=128 chunks with M^CH (batch 16) ---------
__global__ void scan_carry_kernel() {
    int p = threadIdx.x;
    int b = blockIdx.x;
    float4 Mp = g_Mp[p];
    float h1r = 0.f, h1i = 0.f, h2r = 0.f, h2i = 0.f;
    for (int c0 = 0; c0 < NC; c0 += 16) {
        float4 s[16];
        #pragma unroll
        for (int j = 0; j < 16; j++)
            s[j] = g_csum[(b*NC + c0 + j)*PDIM + p];
        #pragma unroll
        for (int j = 0; j < 16; j++) {
            g_cin[(b*NC + c0 + j)*PDIM + p] = make_float4(h1r, h1i, h2r, h2i);
            float n1r = Mp.x*h1r + Mp.y*h2r + s[j].x;
            float n1i = Mp.x*h1i + Mp.y*h2i + s[j].y;
            float n2r = Mp.z*h1r + Mp.w*h2r + s[j].z;
            float n2i = Mp.z*h1i + Mp.w*h2i + s[j].w;
            h1r = n1r; h1i = n1i; h2r = n2r; h2i = n2i;
        }
    }
}

// ---------------- fused final: M=64 tile, scan + GEMM2 + D*x (R11 version) ----
// SMEM (68.6 KB -> 3 CTAs/SM): Ys [64][PY] half (33792B, Bu then ys in place)
//                              Wh [128][PB] half (34816B, W2 K-half)
__global__ void __launch_bounds__(256, 3)
fused_final_kernel(float* __restrict__ outp, const float* __restrict__ x,
                   const float* __restrict__ Dv) {
    extern __shared__ __align__(16) char smem[];
    __half* Ys = (__half*)smem;                          // 33792 B
    __half* Wh = (__half*)(smem + 33792);                // 34816 B
    uint32_t sY = smem_u32(Ys), sW = smem_u32(Wh);
    int tid = threadIdx.x, lane = tid & 31, wid = tid >> 5;
    int wm = wid >> 1, wn = wid & 1;
    int g = lane >> 2, t = lane & 3;
    int c = blockIdx.x, b = blockIdx.y;
    int bm = b*LEN_ + c*CH;                              // global row base (64 rows)
    uint32_t arow = (uint32_t)(lane & 15);
    uint32_t asel = (uint32_t)((lane >> 4) * 8);

    float4 hin;
    if (tid < 128) hin = g_cin[(b*NC + c)*PDIM + tid];

    // load Bu chunk into Ys buffer: 64 rows x 32 uint4, pitch 33 uint4/row
    {
        const uint4* src = (const uint4*)&g_Buh[(size_t)bm*PDIM];
        uint4* dst = (uint4*)Ys;
        #pragma unroll
        for (int i = 0; i < 8; i++) {
            int flat = i*256 + tid;
            int l = flat >> 5, j = flat & 31;
            dst[l*33 + j] = src[flat];
        }
    }
    __syncthreads();

    if (tid < 128) {
        int p = tid;
        float4 Mv = g_M[p];
        float2 cv = g_c[p];
        float h1r = hin.x, h1i = hin.y, h2r = hin.z, h2i = hin.w;
        #pragma unroll 8
        for (int l = 0; l < CH; l++) {
            __half2* slot = (__half2*)&Ys[l*PY + 2*p];
            float2 bu = __half22float2(*slot);
            float n1r = Mv.x*h1r + Mv.y*h2r + cv.x*bu.x;
            float n1i = Mv.x*h1i + Mv.y*h2i + cv.x*bu.y;
            float n2r = Mv.z*h1r + Mv.w*h2r + cv.y*bu.x;
            float n2i = Mv.z*h1i + Mv.w*h2i + cv.y*bu.y;
            h1r = n1r; h1i = n1i; h2r = n2r; h2i = n2i;
            *slot = __floats2half2_rn(h2r, h2i);
        }
    } else {
        int t2 = tid - 128;
        #pragma unroll
        for (int i = 0; i < 16; i++) {
            int flat = i*128 + t2;
            int k = flat >> 4, ch = flat & 15;
            *(uint4*)&Wh[k*PB + ch*8] = *(const uint4*)&g_W2t[(size_t)k*HDIM + ch*8];
        }
    }
    __syncthreads();

    float acc[8][4] = {};
    #pragma unroll
    for (int r = 0; r < 2; r++) {
        if (r) {
            __syncthreads();
            #pragma unroll
            for (int i = 0; i < 8; i++) {
                int flat = i*256 + tid;
                int k = flat >> 4, ch = flat & 15;
                *(uint4*)&Wh[k*PB + ch*8] =
                    *(const uint4*)&g_W2t[(size_t)(128 + k)*HDIM + ch*8];
            }
            __syncthreads();
        }
        #pragma unroll
        for (int ks = 0; ks < 8; ks++) {
            int k0 = ks*16;
            uint32_t a[4], bfr[8][2];
            ldsm4(sY + ((wm*16 + arow)*PY + r*128 + k0 + asel)*2, a);
            #pragma unroll
            for (int np = 0; np < 4; np++) {
                uint32_t rr[4];
                ldsm4t(sW + ((k0 + arow)*PB + wn*64 + np*16 + asel)*2, rr);
                bfr[np*2][0] = rr[0]; bfr[np*2][1] = rr[1];
                bfr[np*2+1][0] = rr[2]; bfr[np*2+1][1] = rr[3];
            }
            #pragma unroll
            for (int nf = 0; nf < 8; nf++)
                mma_f16(acc[nf], a, bfr[nf]);
        }
    }

    {
        int row = bm + wm*16 + g;
        #pragma unroll
        for (int nf = 0; nf < 8; nf++) {
            int col = wn*64 + nf*8 + 2*t;
            float2 d0 = *(const float2*)&Dv[col];
            float2 x0 = *(const float2*)&x[(size_t)row*128 + col];
            float2 x1 = *(const float2*)&x[(size_t)(row+8)*128 + col];
            float2 o0 = make_float2(acc[nf][0] + d0.x*x0.x, acc[nf][1] + d0.y*x0.y);
            float2 o1 = make_float2(acc[nf][2] + d0.x*x1.x, acc[nf][3] + d0.y*x1.y);
            *(float2*)&outp[(size_t)row*128 + col]     = o0;
            *(float2*)&outp[(size_t)(row+8)*128 + col] = o1;
        }
    }
}

// ---------------- launch ------------------------------------------------------
extern "C" void kernel_launch(void* const* d_in, const int* in_sizes, int n_in,
                              void* d_out, int out_size) {
    const float* x  = (const float*)d_in[0];
    const float* Ad = (const float*)d_in[1];
    const float* Gd = (const float*)d_in[2];
    const float* dt = (const float*)d_in[3];
    const float* B  = (const float*)d_in[4];
    const float* C  = (const float*)d_in[5];
    const float* D  = (const float*)d_in[6];
    float* out = (float*)d_out;

    const int SMEM1 = 3 * 34816;                        // 104448
    const int SMEMF = 33792 + 34816;                    // 68608
    cudaFuncSetAttribute(gemm1_kernel, cudaFuncAttributeMaxDynamicSharedMemorySize, SMEM1);
    cudaFuncSetAttribute(fused_final_kernel, cudaFuncAttributeMaxDynamicSharedMemorySize, SMEMF);

    prep_kernel<<<32, 256>>>(Ad, Gd, dt, B, C);
    gemm1_kernel<<<MROWS/128, 256, SMEM1>>>(x);
    scan_carry_kernel<<<BSZ_, 128>>>();
    fused_final_kernel<<<dim3(NC, BSZ_), 256, SMEMF>>>(out, x, D);
}